// round 1
// baseline (speedup 1.0000x reference)
#include <cuda_runtime.h>
#include <math.h>

// Problem constants
#define MTOT 16384      // B*T = 4*4096
#define DIN  1024
#define DSZ  256
#define SNUM 4

// Scratch (allocation-free rule: __device__ globals)
__device__ float g1buf [(size_t)SNUM * MTOT * DSZ];
__device__ float drebuf[(size_t)SNUM * MTOT * DSZ];
__device__ float dimbuf[(size_t)SNUM * MTOT * DSZ];
__device__ float omgbuf[(size_t)SNUM * MTOT * DSZ];

// ---------------------------------------------------------------------------
// Kernel A: the three K=1024 GEMMs fused over a virtual N=3072 column space.
//   columns [0,1024)  -> g1  = relu(x@Wg1[s] + bg1[s])
//   columns [1024,2048) -> dre =      x@Wdr[s] + bdr[s]
//   columns [2048,3072) -> dim =      x@Wdi[s] + bdi[s]
// Classic 128x128x16 sgemm tile, 256 threads, 8x8 per thread.
// ---------------------------------------------------------------------------
__global__ __launch_bounds__(256) void fused_gemm1(
    const float* __restrict__ x,
    const float* __restrict__ Wg1, const float* __restrict__ bg1,
    const float* __restrict__ Wdr, const float* __restrict__ bdr,
    const float* __restrict__ Wdi, const float* __restrict__ bdi)
{
    __shared__ __align__(16) float As[16][128];
    __shared__ __align__(16) float Bs[16][128];

    const int tid   = threadIdx.x;
    const int mbase = blockIdx.x * 128;
    const int nb    = blockIdx.y * 128;   // 0..3071
    const int mat   = nb >> 10;           // 0=g1, 1=dre, 2=dim
    const int rem   = nb & 1023;
    const int s     = rem >> 8;
    const int dbase = rem & 255;          // 0 or 128

    const float* W;
    const float* bias;
    float* outp;
    if (mat == 0)      { W = Wg1; bias = bg1; outp = g1buf; }
    else if (mat == 1) { W = Wdr; bias = bdr; outp = drebuf; }
    else               { W = Wdi; bias = bdi; outp = dimbuf; }
    W    += (size_t)s * DIN * DSZ;
    bias += s * DSZ;
    outp += (size_t)s * MTOT * DSZ;

    const int aRow = tid >> 2;            // 0..63
    const int aCol = (tid & 3) << 2;      // 0,4,8,12
    const int bRow = tid >> 5;            // 0..7
    const int bCol = (tid & 31) << 2;     // 0..124

    const int tRow = (tid >> 4) << 3;     // 0..120
    const int tCol = (tid & 15) << 3;     // 0..120

    float acc[8][8];
#pragma unroll
    for (int i = 0; i < 8; i++)
#pragma unroll
        for (int j = 0; j < 8; j++) acc[i][j] = 0.f;

    for (int k0 = 0; k0 < DIN; k0 += 16) {
#pragma unroll
        for (int r = 0; r < 2; r++) {
            int row = aRow + r * 64;
            float4 v = *(const float4*)&x[(size_t)(mbase + row) * DIN + k0 + aCol];
            As[aCol + 0][row] = v.x;
            As[aCol + 1][row] = v.y;
            As[aCol + 2][row] = v.z;
            As[aCol + 3][row] = v.w;
        }
#pragma unroll
        for (int r = 0; r < 2; r++) {
            int k = bRow + r * 8;
            *(float4*)&Bs[k][bCol] =
                *(const float4*)&W[(size_t)(k0 + k) * DSZ + dbase + bCol];
        }
        __syncthreads();
#pragma unroll
        for (int k = 0; k < 16; k++) {
            float rm[8], rn[8];
            *(float4*)&rm[0] = *(const float4*)&As[k][tRow];
            *(float4*)&rm[4] = *(const float4*)&As[k][tRow + 4];
            *(float4*)&rn[0] = *(const float4*)&Bs[k][tCol];
            *(float4*)&rn[4] = *(const float4*)&Bs[k][tCol + 4];
#pragma unroll
            for (int i = 0; i < 8; i++)
#pragma unroll
                for (int j = 0; j < 8; j++)
                    acc[i][j] = fmaf(rm[i], rn[j], acc[i][j]);
        }
        __syncthreads();
    }

    float bv[8];
#pragma unroll
    for (int j = 0; j < 8; j++) bv[j] = bias[dbase + tCol + j];
#pragma unroll
    for (int i = 0; i < 8; i++) {
        int m = mbase + tRow + i;
        float o[8];
#pragma unroll
        for (int j = 0; j < 8; j++) {
            float v = acc[i][j] + bv[j];
            if (mat == 0) v = fmaxf(v, 0.f);
            o[j] = v;
        }
        *(float4*)&outp[(size_t)m * DSZ + dbase + tCol]     = *(float4*)&o[0];
        *(float4*)&outp[(size_t)m * DSZ + dbase + tCol + 4] = *(float4*)&o[4];
    }
}

// ---------------------------------------------------------------------------
// Kernel B: gate GEMM per scale. omg = 1 - sigmoid(g1@Wg2[s] + bg2[s]).
// K=256. Same tile structure.
// ---------------------------------------------------------------------------
__global__ __launch_bounds__(256) void fused_gemm2(
    const float* __restrict__ Wg2, const float* __restrict__ bg2)
{
    __shared__ __align__(16) float As[16][128];
    __shared__ __align__(16) float Bs[16][128];

    const int tid   = threadIdx.x;
    const int mbase = blockIdx.x * 128;
    const int s     = blockIdx.y >> 1;
    const int dbase = (blockIdx.y & 1) * 128;

    const float* A    = g1buf + (size_t)s * MTOT * DSZ;
    const float* W    = Wg2 + (size_t)s * DSZ * DSZ;
    const float* bias = bg2 + s * DSZ;
    float* outp       = omgbuf + (size_t)s * MTOT * DSZ;

    const int aRow = tid >> 2;
    const int aCol = (tid & 3) << 2;
    const int bRow = tid >> 5;
    const int bCol = (tid & 31) << 2;
    const int tRow = (tid >> 4) << 3;
    const int tCol = (tid & 15) << 3;

    float acc[8][8];
#pragma unroll
    for (int i = 0; i < 8; i++)
#pragma unroll
        for (int j = 0; j < 8; j++) acc[i][j] = 0.f;

    for (int k0 = 0; k0 < DSZ; k0 += 16) {
#pragma unroll
        for (int r = 0; r < 2; r++) {
            int row = aRow + r * 64;
            float4 v = *(const float4*)&A[(size_t)(mbase + row) * DSZ + k0 + aCol];
            As[aCol + 0][row] = v.x;
            As[aCol + 1][row] = v.y;
            As[aCol + 2][row] = v.z;
            As[aCol + 3][row] = v.w;
        }
#pragma unroll
        for (int r = 0; r < 2; r++) {
            int k = bRow + r * 8;
            *(float4*)&Bs[k][bCol] =
                *(const float4*)&W[(size_t)(k0 + k) * DSZ + dbase + bCol];
        }
        __syncthreads();
#pragma unroll
        for (int k = 0; k < 16; k++) {
            float rm[8], rn[8];
            *(float4*)&rm[0] = *(const float4*)&As[k][tRow];
            *(float4*)&rm[4] = *(const float4*)&As[k][tRow + 4];
            *(float4*)&rn[0] = *(const float4*)&Bs[k][tCol];
            *(float4*)&rn[4] = *(const float4*)&Bs[k][tCol + 4];
#pragma unroll
            for (int i = 0; i < 8; i++)
#pragma unroll
                for (int j = 0; j < 8; j++)
                    acc[i][j] = fmaf(rm[i], rn[j], acc[i][j]);
        }
        __syncthreads();
    }

    float bv[8];
#pragma unroll
    for (int j = 0; j < 8; j++) bv[j] = bias[dbase + tCol + j];
#pragma unroll
    for (int i = 0; i < 8; i++) {
        int m = mbase + tRow + i;
        float o[8];
#pragma unroll
        for (int j = 0; j < 8; j++) {
            float z = acc[i][j] + bv[j];
            // 1 - sigmoid(z) == 1/(1+exp(z))
            o[j] = 1.0f / (1.0f + __expf(z) * 0.0f + expf(z));
        }
        *(float4*)&outp[(size_t)m * DSZ + dbase + tCol]     = *(float4*)&o[0];
        *(float4*)&outp[(size_t)m * DSZ + dbase + tCol + 4] = *(float4*)&o[4];
    }
}

// ---------------------------------------------------------------------------
// Kernel C: sequential complex linear recurrence along T, lane = d channel.
// One block per (b,s): 256 threads = 256 d-channels, coalesced in d.
//   h_t = (omg*a_base) * h_{t-1} + omg*bscale*(dre + i*dim)
// Output layout: out[b][t][s*512 + d] = Re, out[b][t][s*512 + 256 + d] = Im.
// ---------------------------------------------------------------------------
struct ScanConsts { float abr[4], abi[4], bsc[4]; };

__global__ __launch_bounds__(256) void scan_kernel(float* __restrict__ out, ScanConsts c)
{
    const int b = blockIdx.x >> 2;
    const int s = blockIdx.x & 3;
    const int d = threadIdx.x;

    const float abr = c.abr[s], abi = c.abi[s], bs = c.bsc[s];
    const size_t base = ((size_t)s * MTOT + (size_t)b * 4096) * DSZ + d;
    const float* om = omgbuf + base;
    const float* dr = drebuf + base;
    const float* di = dimbuf + base;
    float* op = out + (size_t)b * 4096 * 2048 + (size_t)s * 512 + d;

    float hr = 0.f, hi = 0.f;
#pragma unroll 4
    for (int t = 0; t < 4096; t++) {
        const size_t off = (size_t)t * DSZ;
        float w  = om[off];
        float xr = dr[off];
        float xi = di[off];
        float ar = w * abr;
        float ai = w * abi;
        float wb = w * bs;
        float br_ = wb * xr;
        float bi_ = wb * xi;
        float nhr = fmaf(ar, hr, fmaf(-ai, hi, br_));
        float nhi = fmaf(ar, hi, fmaf( ai, hr, bi_));
        hr = nhr; hi = nhi;
        op[(size_t)t * 2048]       = hr;
        op[(size_t)t * 2048 + 256] = hi;
    }
}

// ---------------------------------------------------------------------------
extern "C" void kernel_launch(void* const* d_in, const int* in_sizes, int n_in,
                              void* d_out, int out_size)
{
    const float* x   = (const float*)d_in[0];
    const float* Wg1 = (const float*)d_in[1];
    const float* bg1 = (const float*)d_in[2];
    const float* Wg2 = (const float*)d_in[3];
    const float* bg2 = (const float*)d_in[4];
    const float* Wdr = (const float*)d_in[5];
    const float* bdr = (const float*)d_in[6];
    const float* Wdi = (const float*)d_in[7];
    const float* bdi = (const float*)d_in[8];
    float* out = (float*)d_out;

    dim3 gA(MTOT / 128, 24);
    fused_gemm1<<<gA, 256>>>(x, Wg1, bg1, Wdr, bdr, Wdi, bdi);

    dim3 gB(MTOT / 128, 8);
    fused_gemm2<<<gB, 256>>>(Wg2, bg2);

    // scale constants: r = [1, linspace(0.999, 0.9, 3)], theta = [0, linspace(0.01, 1, 3)]
    ScanConsts c;
    const double r [4] = {1.0, 0.999, 0.9495, 0.9};
    const double th[4] = {0.0, 0.01,  0.505,  1.0};
    for (int s = 0; s < 4; s++) {
        c.abr[s] = (float)(r[s] * cos(th[s]));
        c.abi[s] = (float)(r[s] * sin(th[s]));
        c.bsc[s] = (float)((r[s] >= 1.0) ? (1.0 / 16.0) : (1.0 - r[s]));
    }
    scan_kernel<<<16, 256>>>(out, c);
}

// round 3
// speedup vs baseline: 4.1885x; 4.1885x over previous
#include <cuda_runtime.h>
#include <cuda_fp16.h>
#include <stdint.h>
#include <math.h>

#define MTOT 16384
#define DIN  1024
#define DSZ  256
#define KCH  32            // k-halfs per pipeline chunk
#define LDR  80            // padded SMEM row stride in bytes (40 halfs)
#define PL_A (128 * LDR)   // 10240 bytes per plane (128 rows)
#define STG  (3 * PL_A)    // Ahi, Alo, B planes per stage
#define NST  3
#define SMEM_SZ (NST * STG)

// ---------------- scratch (__device__ globals; no allocations) ----------------
__device__ __half xhi_g[(size_t)MTOT * DIN];
__device__ __half xlo_g[(size_t)MTOT * DIN];
__device__ __half w1f16_g[(size_t)12 * DSZ * DIN];   // [mat*4+s][n=d][k]
__device__ __half w2f16_g[(size_t)4 * DSZ * DSZ];    // [s][n=e][k]
__device__ __half g1hi_g[(size_t)4 * MTOT * DSZ];
__device__ __half g1lo_g[(size_t)4 * MTOT * DSZ];
__device__ float dre_g[(size_t)4 * MTOT * DSZ];
__device__ float dim_g[(size_t)4 * MTOT * DSZ];
__device__ float omg_g[(size_t)4 * MTOT * DSZ];
__device__ float2 Aseg_g[256 * 256];
__device__ float2 Hseg_g[256 * 256];
__device__ float2 Ini_g [256 * 256];

// ---------------- PTX helpers (baseline ISA only: sm_80-class features) --------
__device__ __forceinline__ uint32_t smem_u32(const void* p) {
    uint32_t a;
    asm("{ .reg .u64 t; cvta.to.shared.u64 t, %1; cvt.u32.u64 %0, t; }" : "=r"(a) : "l"(p));
    return a;
}
__device__ __forceinline__ void cpa16(uint32_t dst, const void* src) {
    asm volatile("cp.async.cg.shared.global [%0], [%1], 16;" :: "r"(dst), "l"(src));
}
__device__ __forceinline__ void cpa_commit() {
    asm volatile("cp.async.commit_group;");
}
template<int N> __device__ __forceinline__ void cpa_wait() {
    asm volatile("cp.async.wait_group %0;" :: "n"(N));
}
__device__ __forceinline__ void ldsm4(uint32_t r[4], uint32_t addr) {
    asm volatile("ldmatrix.sync.aligned.m8n8.x4.shared.b16 {%0,%1,%2,%3}, [%4];"
        : "=r"(r[0]), "=r"(r[1]), "=r"(r[2]), "=r"(r[3]) : "r"(addr));
}
__device__ __forceinline__ void mma_f16(float c[4], const uint32_t a[4], const uint32_t b[2]) {
    asm volatile("mma.sync.aligned.m16n8k16.row.col.f32.f16.f16.f32 "
        "{%0,%1,%2,%3}, {%4,%5,%6,%7}, {%8,%9}, {%0,%1,%2,%3};"
        : "+f"(c[0]), "+f"(c[1]), "+f"(c[2]), "+f"(c[3])
        : "r"(a[0]), "r"(a[1]), "r"(a[2]), "r"(a[3]), "r"(b[0]), "r"(b[1]));
}

// ---------------- GEMM pipeline core -------------------------------------------
// C[128,128] tile = (Ahi+Alo)[128,K] x B^T[128,K], fp32 accum, 2-pass fp16 split.
// 8 warps: wm = warp&3 (m 32-band), wn = warp>>2 (n 64-band).
template<int NCH>
__device__ __forceinline__ void gemm_pipeline(
    const __half* __restrict__ gAh, const __half* __restrict__ gAl,
    const __half* __restrict__ gB, const int ldk,
    uint32_t s0, float acc[2][8][4])
{
    const int tid = threadIdx.x;

    auto issue = [&](int st, int k0) {
        uint32_t base = s0 + st * STG;
#pragma unroll
        for (int it = 0; it < 2; it++) {
            int q = tid + it * 256;
            int r = q >> 2, c = q & 3;
            uint32_t off = base + r * LDR + c * 16;
            size_t go = (size_t)r * ldk + k0 + c * 8;
            cpa16(off,            gAh + go);
            cpa16(off + PL_A,     gAl + go);
            cpa16(off + 2 * PL_A, gB + go);
        }
        cpa_commit();
    };

#pragma unroll
    for (int i = 0; i < 2; i++)
#pragma unroll
        for (int j = 0; j < 8; j++)
#pragma unroll
            for (int k = 0; k < 4; k++) acc[i][j][k] = 0.f;

    issue(0, 0);
    issue(1, KCH);

    const int lane = tid & 31, warp = tid >> 5;
    const int wm = warp & 3, wn = warp >> 2;
    const uint32_t aBase = (uint32_t)(wm * 32 + (lane & 15)) * LDR + (lane >> 4) * 16;
    const uint32_t bBase = (uint32_t)(wn * 64 + (lane & 7) + ((lane & 16) >> 1)) * LDR
                         + ((lane >> 3) & 1) * 16;

    for (int ch = 0; ch < NCH; ch++) {
        if (ch == NCH - 1) cpa_wait<0>(); else cpa_wait<1>();
        __syncthreads();
        const uint32_t sb = s0 + (ch % 3) * STG;
#pragma unroll
        for (int ks = 0; ks < 2; ks++) {
            uint32_t ah[2][4], al[2][4], bb[4][4];
#pragma unroll
            for (int mi = 0; mi < 2; mi++) {
                uint32_t ad = sb + aBase + mi * (16 * LDR) + ks * 32;
                ldsm4(ah[mi], ad);
                ldsm4(al[mi], ad + PL_A);
            }
#pragma unroll
            for (int nf4 = 0; nf4 < 4; nf4++)
                ldsm4(bb[nf4], sb + 2 * PL_A + bBase + nf4 * (16 * LDR) + ks * 32);
#pragma unroll
            for (int mi = 0; mi < 2; mi++)
#pragma unroll
                for (int nf = 0; nf < 8; nf++) {
                    const uint32_t* bp = &bb[nf >> 1][(nf & 1) * 2];
                    mma_f16(acc[mi][nf], ah[mi], bp);
                    mma_f16(acc[mi][nf], al[mi], bp);
                }
        }
        if (ch + 2 < NCH) issue((ch + 2) % 3, (ch + 2) * KCH);
    }
}

// ---------------- GEMM 1: x @ {Wg1,Wdr,Wdi} -----------------------------------
__global__ __launch_bounds__(256) void gemm1_k(
    const float* __restrict__ bg1, const float* __restrict__ bdr, const float* __restrict__ bdi)
{
    extern __shared__ char sm[];
    uint32_t s0 = smem_u32(sm);

    const int mbase = blockIdx.x * 128;
    const int nb = blockIdx.y;                 // 0..23
    const int mat = nb >> 3;                   // 0=g1, 1=dre, 2=dim
    const int s = (nb >> 1) & 3;
    const int dbase = (nb & 1) * 128;

    const __half* gAh = xhi_g + (size_t)mbase * DIN;
    const __half* gAl = xlo_g + (size_t)mbase * DIN;
    const __half* gB  = w1f16_g + ((size_t)(mat * 4 + s) * DSZ + dbase) * DIN;

    float acc[2][8][4];
    gemm_pipeline<DIN / KCH>(gAh, gAl, gB, DIN, s0, acc);

    const int lane = threadIdx.x & 31, warp = threadIdx.x >> 5;
    const int wm = warp & 3, wn = warp >> 2;
    const int r0 = mbase + wm * 32 + (lane >> 2);
    const int c0 = wn * 64 + (lane & 3) * 2;
    const float* bias = (mat == 0 ? bg1 : (mat == 1 ? bdr : bdi)) + s * DSZ + dbase;

    if (mat == 0) {
        __half* oh = g1hi_g + (size_t)s * MTOT * DSZ;
        __half* ol = g1lo_g + (size_t)s * MTOT * DSZ;
#pragma unroll
        for (int mi = 0; mi < 2; mi++)
#pragma unroll
            for (int nf = 0; nf < 8; nf++) {
                int col = c0 + nf * 8;
                float b0 = bias[col], b1 = bias[col + 1];
#pragma unroll
                for (int hh = 0; hh < 2; hh++) {
                    int r = r0 + mi * 16 + hh * 8;
                    float v0 = fmaxf(acc[mi][nf][hh * 2 + 0] + b0, 0.f);
                    float v1 = fmaxf(acc[mi][nf][hh * 2 + 1] + b1, 0.f);
                    __half h0 = __float2half_rn(v0);
                    __half h1 = __float2half_rn(v1);
                    __half l0 = __float2half_rn(v0 - __half2float(h0));
                    __half l1 = __float2half_rn(v1 - __half2float(h1));
                    size_t o = ((size_t)r) * DSZ + dbase + col;
                    *(__half2*)(oh + o) = __halves2half2(h0, h1);
                    *(__half2*)(ol + o) = __halves2half2(l0, l1);
                }
            }
    } else {
        float* op = (mat == 1 ? dre_g : dim_g) + (size_t)s * MTOT * DSZ;
#pragma unroll
        for (int mi = 0; mi < 2; mi++)
#pragma unroll
            for (int nf = 0; nf < 8; nf++) {
                int col = c0 + nf * 8;
                float b0 = bias[col], b1 = bias[col + 1];
#pragma unroll
                for (int hh = 0; hh < 2; hh++) {
                    int r = r0 + mi * 16 + hh * 8;
                    float2 v;
                    v.x = acc[mi][nf][hh * 2 + 0] + b0;
                    v.y = acc[mi][nf][hh * 2 + 1] + b1;
                    *(float2*)(op + (size_t)r * DSZ + dbase + col) = v;
                }
            }
    }
}

// ---------------- GEMM 2: omg = 1 - sigmoid(g1 @ Wg2 + bg2) --------------------
__global__ __launch_bounds__(256) void gemm2_k(const float* __restrict__ bg2)
{
    extern __shared__ char sm[];
    uint32_t s0 = smem_u32(sm);

    const int mbase = blockIdx.x * 128;
    const int s = blockIdx.y >> 1;
    const int dbase = (blockIdx.y & 1) * 128;

    const __half* gAh = g1hi_g + ((size_t)s * MTOT + mbase) * DSZ;
    const __half* gAl = g1lo_g + ((size_t)s * MTOT + mbase) * DSZ;
    const __half* gB  = w2f16_g + ((size_t)s * DSZ + dbase) * DSZ;

    float acc[2][8][4];
    gemm_pipeline<DSZ / KCH>(gAh, gAl, gB, DSZ, s0, acc);

    const int lane = threadIdx.x & 31, warp = threadIdx.x >> 5;
    const int wm = warp & 3, wn = warp >> 2;
    const int r0 = mbase + wm * 32 + (lane >> 2);
    const int c0 = wn * 64 + (lane & 3) * 2;
    const float* bias = bg2 + s * DSZ + dbase;
    float* op = omg_g + (size_t)s * MTOT * DSZ;

#pragma unroll
    for (int mi = 0; mi < 2; mi++)
#pragma unroll
        for (int nf = 0; nf < 8; nf++) {
            int col = c0 + nf * 8;
            float b0 = bias[col], b1 = bias[col + 1];
#pragma unroll
            for (int hh = 0; hh < 2; hh++) {
                int r = r0 + mi * 16 + hh * 8;
                float2 v;
                v.x = 1.0f / (1.0f + expf(acc[mi][nf][hh * 2 + 0] + b0));
                v.y = 1.0f / (1.0f + expf(acc[mi][nf][hh * 2 + 1] + b1));
                *(float2*)(op + (size_t)r * DSZ + dbase + col) = v;
            }
        }
}

// ---------------- conversion kernels -------------------------------------------
__global__ __launch_bounds__(256) void conv_x_k(const float* __restrict__ x) {
    size_t i = ((size_t)blockIdx.x * 256 + threadIdx.x) * 4;
    float4 v = *(const float4*)(x + i);
    float f[4] = {v.x, v.y, v.z, v.w};
    union { __half h[4]; uint2 u; } ph, pl;
#pragma unroll
    for (int j = 0; j < 4; j++) {
        __half h = __float2half_rn(f[j]);
        ph.h[j] = h;
        pl.h[j] = __float2half_rn(f[j] - __half2float(h));
    }
    *(uint2*)(xhi_g + i) = ph.u;
    *(uint2*)(xlo_g + i) = pl.u;
}

__global__ void conv_w1_k(const float* __restrict__ src, int zbase, int kdim) {
    __shared__ float t[32][33];
    int z = blockIdx.z;
    const float* sp = src + (size_t)z * kdim * DSZ;
    int tx = threadIdx.x, ty = threadIdx.y;
    int k0 = blockIdx.x * 32, d0 = blockIdx.y * 32;
#pragma unroll
    for (int i = 0; i < 4; i++)
        t[ty + i * 8][tx] = sp[(size_t)(k0 + ty + i * 8) * DSZ + d0 + tx];
    __syncthreads();
    __half* oh = (kdim == DIN ? w1f16_g + (size_t)(zbase + z) * DSZ * DIN
                              : w2f16_g + (size_t)z * DSZ * DSZ);
#pragma unroll
    for (int i = 0; i < 4; i++) {
        int n = d0 + ty + i * 8, k = k0 + tx;
        oh[(size_t)n * kdim + k] = __float2half_rn(t[tx][ty + i * 8]);
    }
}

// ---------------- segmented scan (3 phases) ------------------------------------
struct ScanConsts { float abr[4], abi[4], bsc[4]; };

__global__ __launch_bounds__(256) void scan_p1(ScanConsts c) {
    const int idx = blockIdx.x;                 // b*64 + s*16 + seg
    const int seg = idx & 15, s = (idx >> 4) & 3, b = idx >> 6;
    const int d = threadIdx.x;
    const float abr = c.abr[s], abi = c.abi[s], bs = c.bsc[s];
    const size_t base = ((size_t)s * MTOT + (size_t)b * 4096 + seg * 256) * DSZ + d;
    float Ar = 1.f, Ai = 0.f, Hr = 0.f, Hi = 0.f;
#pragma unroll 4
    for (int t = 0; t < 256; t++) {
        size_t off = base + (size_t)t * DSZ;
        float w  = omg_g[off];
        float xr = dre_g[off];
        float xi = dim_g[off];
        float ar = w * abr, ai = w * abi, wb = w * bs;
        float br = wb * xr, bi = wb * xi;
        float nHr = fmaf(ar, Hr, fmaf(-ai, Hi, br));
        float nHi = fmaf(ar, Hi, fmaf( ai, Hr, bi));
        float nAr = fmaf(ar, Ar, -ai * Ai);
        float nAi = fmaf(ar, Ai,  ai * Ar);
        Hr = nHr; Hi = nHi; Ar = nAr; Ai = nAi;
    }
    Aseg_g[idx * 256 + d] = make_float2(Ar, Ai);
    Hseg_g[idx * 256 + d] = make_float2(Hr, Hi);
}

__global__ __launch_bounds__(256) void scan_p2() {
    const int bs_ = blockIdx.x;                 // b*4 + s
    const int d = threadIdx.x;
    float cr = 0.f, ci = 0.f;
#pragma unroll
    for (int g = 0; g < 16; g++) {
        int idx = (bs_ * 16 + g) * 256 + d;
        Ini_g[idx] = make_float2(cr, ci);
        float2 A = Aseg_g[idx];
        float2 H = Hseg_g[idx];
        float ncr = fmaf(A.x, cr, fmaf(-A.y, ci, H.x));
        float nci = fmaf(A.x, ci, fmaf( A.y, cr, H.y));
        cr = ncr; ci = nci;
    }
}

__global__ __launch_bounds__(256) void scan_p3(float* __restrict__ out, ScanConsts c) {
    const int idx = blockIdx.x;
    const int seg = idx & 15, s = (idx >> 4) & 3, b = idx >> 6;
    const int d = threadIdx.x;
    const float abr = c.abr[s], abi = c.abi[s], bs = c.bsc[s];
    const size_t base = ((size_t)s * MTOT + (size_t)b * 4096 + seg * 256) * DSZ + d;
    float2 h0 = Ini_g[idx * 256 + d];
    float hr = h0.x, hi = h0.y;
    float* op = out + ((size_t)b * 4096 + seg * 256) * 2048 + (size_t)s * 512 + d;
#pragma unroll 4
    for (int t = 0; t < 256; t++) {
        size_t off = base + (size_t)t * DSZ;
        float w  = omg_g[off];
        float xr = dre_g[off];
        float xi = dim_g[off];
        float ar = w * abr, ai = w * abi, wb = w * bs;
        float br = wb * xr, bi = wb * xi;
        float nhr = fmaf(ar, hr, fmaf(-ai, hi, br));
        float nhi = fmaf(ar, hi, fmaf( ai, hr, bi));
        hr = nhr; hi = nhi;
        op[(size_t)t * 2048]       = hr;
        op[(size_t)t * 2048 + 256] = hi;
    }
}

// ---------------- host ----------------------------------------------------------
extern "C" void kernel_launch(void* const* d_in, const int* in_sizes, int n_in,
                              void* d_out, int out_size)
{
    const float* x   = (const float*)d_in[0];
    const float* Wg1 = (const float*)d_in[1];
    const float* bg1 = (const float*)d_in[2];
    const float* Wg2 = (const float*)d_in[3];
    const float* bg2 = (const float*)d_in[4];
    const float* Wdr = (const float*)d_in[5];
    const float* bdr = (const float*)d_in[6];
    const float* Wdi = (const float*)d_in[7];
    const float* bdi = (const float*)d_in[8];
    float* out = (float*)d_out;

    cudaFuncSetAttribute(gemm1_k, cudaFuncAttributeMaxDynamicSharedMemorySize, SMEM_SZ);
    cudaFuncSetAttribute(gemm2_k, cudaFuncAttributeMaxDynamicSharedMemorySize, SMEM_SZ);

    conv_x_k<<<(int)(((size_t)MTOT * DIN) / 1024), 256>>>(x);
    dim3 tb(32, 8);
    conv_w1_k<<<dim3(32, 8, 4), tb>>>(Wg1, 0, DIN);
    conv_w1_k<<<dim3(32, 8, 4), tb>>>(Wdr, 4, DIN);
    conv_w1_k<<<dim3(32, 8, 4), tb>>>(Wdi, 8, DIN);
    conv_w1_k<<<dim3(8, 8, 4), tb>>>(Wg2, 0, DSZ);

    gemm1_k<<<dim3(MTOT / 128, 24), 256, SMEM_SZ>>>(bg1, bdr, bdi);
    gemm2_k<<<dim3(MTOT / 128, 8), 256, SMEM_SZ>>>(bg2);

    ScanConsts c;
    const double r [4] = {1.0, 0.999, 0.9495, 0.9};
    const double th[4] = {0.0, 0.01,  0.505,  1.0};
    for (int s = 0; s < 4; s++) {
        c.abr[s] = (float)(r[s] * cos(th[s]));
        c.abi[s] = (float)(r[s] * sin(th[s]));
        c.bsc[s] = (float)((r[s] >= 1.0) ? (1.0 / 16.0) : (1.0 - r[s]));
    }
    scan_p1<<<256, 256>>>(c);
    scan_p2<<<16, 256>>>();
    scan_p3<<<256, 256>>>(out, c);
}

// round 4
// speedup vs baseline: 5.2842x; 1.2616x over previous
#include <cuda_runtime.h>
#include <cuda_fp16.h>
#include <stdint.h>
#include <math.h>

#define MTOT 16384
#define DIN  1024
#define DSZ  256
#define KCH  32            // k-halfs per pipeline chunk
#define LDR  80            // padded SMEM row stride in bytes (40 halfs)
#define PL_A (128 * LDR)   // 10240 bytes per plane (128 rows)
#define STG  (2 * PL_A)    // A, B planes per stage
#define NST  4
#define SMEM_SZ (NST * STG)

// ---------------- scratch (__device__ globals; no allocations) ----------------
__device__ __half xh_g[(size_t)MTOT * DIN];
__device__ __half w1f16_g[(size_t)12 * DSZ * DIN];   // [mat*4+s][n=d][k]
__device__ __half w2f16_g[(size_t)4 * DSZ * DSZ];    // [s][n=e][k]
__device__ __half g1f16_g[(size_t)4 * MTOT * DSZ];
__device__ float dre_g[(size_t)4 * MTOT * DSZ];
__device__ float dim_g[(size_t)4 * MTOT * DSZ];
__device__ float omg_g[(size_t)4 * MTOT * DSZ];
__device__ float2 Aseg_g[256 * 256];
__device__ float2 Hseg_g[256 * 256];
__device__ float2 Ini_g [256 * 256];

// ---------------- PTX helpers (baseline ISA only) ------------------------------
__device__ __forceinline__ uint32_t smem_u32(const void* p) {
    uint32_t a;
    asm("{ .reg .u64 t; cvta.to.shared.u64 t, %1; cvt.u32.u64 %0, t; }" : "=r"(a) : "l"(p));
    return a;
}
__device__ __forceinline__ void cpa16(uint32_t dst, const void* src) {
    asm volatile("cp.async.cg.shared.global [%0], [%1], 16;" :: "r"(dst), "l"(src));
}
__device__ __forceinline__ void cpa_commit() {
    asm volatile("cp.async.commit_group;");
}
template<int N> __device__ __forceinline__ void cpa_wait() {
    asm volatile("cp.async.wait_group %0;" :: "n"(N));
}
__device__ __forceinline__ void ldsm4(uint32_t r[4], uint32_t addr) {
    asm volatile("ldmatrix.sync.aligned.m8n8.x4.shared.b16 {%0,%1,%2,%3}, [%4];"
        : "=r"(r[0]), "=r"(r[1]), "=r"(r[2]), "=r"(r[3]) : "r"(addr));
}
__device__ __forceinline__ void mma_f16(float c[4], const uint32_t a[4], const uint32_t b[2]) {
    asm volatile("mma.sync.aligned.m16n8k16.row.col.f32.f16.f16.f32 "
        "{%0,%1,%2,%3}, {%4,%5,%6,%7}, {%8,%9}, {%0,%1,%2,%3};"
        : "+f"(c[0]), "+f"(c[1]), "+f"(c[2]), "+f"(c[3])
        : "r"(a[0]), "r"(a[1]), "r"(a[2]), "r"(a[3]), "r"(b[0]), "r"(b[1]));
}

// ---------------- GEMM pipeline core -------------------------------------------
// C[128,128] = A[128,K] x B^T[128,K], fp32 accum, single fp16 pass.
// 8 warps: wm = warp&3 (m 32-band), wn = warp>>2 (n 64-band). 3-deep prefetch.
template<int NCH>
__device__ __forceinline__ void gemm_pipeline(
    const __half* __restrict__ gA, const __half* __restrict__ gB,
    const int ldk, uint32_t s0, float acc[2][8][4])
{
    const int tid = threadIdx.x;

    auto issue = [&](int st, int k0) {
        uint32_t base = s0 + st * STG;
#pragma unroll
        for (int it = 0; it < 2; it++) {
            int q = tid + it * 256;
            int r = q >> 2, c = q & 3;
            uint32_t off = base + r * LDR + c * 16;
            size_t go = (size_t)r * ldk + k0 + c * 8;
            cpa16(off,        gA + go);
            cpa16(off + PL_A, gB + go);
        }
        cpa_commit();
    };

#pragma unroll
    for (int i = 0; i < 2; i++)
#pragma unroll
        for (int j = 0; j < 8; j++)
#pragma unroll
            for (int k = 0; k < 4; k++) acc[i][j][k] = 0.f;

    issue(0, 0);
    if (NCH > 1) issue(1, KCH);
    if (NCH > 2) issue(2, 2 * KCH);

    const int lane = tid & 31, warp = tid >> 5;
    const int wm = warp & 3, wn = warp >> 2;
    const uint32_t aBase = (uint32_t)(wm * 32 + (lane & 15)) * LDR + (lane >> 4) * 16;
    const uint32_t bBase = (uint32_t)(wn * 64 + (lane & 7) + ((lane & 16) >> 1)) * LDR
                         + ((lane >> 3) & 1) * 16;

    for (int ch = 0; ch < NCH; ch++) {
        // pending allowed = min(2, NCH-1-ch)
        if (ch >= NCH - 1)      cpa_wait<0>();
        else if (ch == NCH - 2) cpa_wait<1>();
        else                    cpa_wait<2>();
        __syncthreads();
        const uint32_t sb = s0 + (ch & (NST - 1)) * STG;
        if (ch + 3 < NCH) issue((ch + 3) & (NST - 1), (ch + 3) * KCH);
#pragma unroll
        for (int ks = 0; ks < 2; ks++) {
            uint32_t ah[2][4], bb[4][4];
#pragma unroll
            for (int mi = 0; mi < 2; mi++)
                ldsm4(ah[mi], sb + aBase + mi * (16 * LDR) + ks * 32);
#pragma unroll
            for (int nf4 = 0; nf4 < 4; nf4++)
                ldsm4(bb[nf4], sb + PL_A + bBase + nf4 * (16 * LDR) + ks * 32);
#pragma unroll
            for (int mi = 0; mi < 2; mi++)
#pragma unroll
                for (int nf = 0; nf < 8; nf++)
                    mma_f16(acc[mi][nf], ah[mi], &bb[nf >> 1][(nf & 1) * 2]);
        }
        __syncthreads();
    }
}

// ---------------- GEMM 1: x @ {Wg1,Wdr,Wdi} -----------------------------------
__global__ __launch_bounds__(256) void gemm1_k(
    const float* __restrict__ bg1, const float* __restrict__ bdr, const float* __restrict__ bdi)
{
    extern __shared__ char sm[];
    uint32_t s0 = smem_u32(sm);

    const int mbase = blockIdx.x * 128;
    const int nb = blockIdx.y;                 // 0..23
    const int mat = nb >> 3;                   // 0=g1, 1=dre, 2=dim
    const int s = (nb >> 1) & 3;
    const int dbase = (nb & 1) * 128;

    const __half* gA = xh_g + (size_t)mbase * DIN;
    const __half* gB = w1f16_g + ((size_t)(mat * 4 + s) * DSZ + dbase) * DIN;

    float acc[2][8][4];
    gemm_pipeline<DIN / KCH>(gA, gB, DIN, s0, acc);

    const int lane = threadIdx.x & 31, warp = threadIdx.x >> 5;
    const int wm = warp & 3, wn = warp >> 2;
    const int r0 = mbase + wm * 32 + (lane >> 2);
    const int c0 = wn * 64 + (lane & 3) * 2;
    const float* bias = (mat == 0 ? bg1 : (mat == 1 ? bdr : bdi)) + s * DSZ + dbase;

    if (mat == 0) {
        __half* oh = g1f16_g + (size_t)s * MTOT * DSZ;
#pragma unroll
        for (int mi = 0; mi < 2; mi++)
#pragma unroll
            for (int nf = 0; nf < 8; nf++) {
                int col = c0 + nf * 8;
                float b0 = bias[col], b1 = bias[col + 1];
#pragma unroll
                for (int hh = 0; hh < 2; hh++) {
                    int r = r0 + mi * 16 + hh * 8;
                    float v0 = fmaxf(acc[mi][nf][hh * 2 + 0] + b0, 0.f);
                    float v1 = fmaxf(acc[mi][nf][hh * 2 + 1] + b1, 0.f);
                    *(__half2*)(oh + (size_t)r * DSZ + dbase + col) =
                        __halves2half2(__float2half_rn(v0), __float2half_rn(v1));
                }
            }
    } else {
        float* op = (mat == 1 ? dre_g : dim_g) + (size_t)s * MTOT * DSZ;
#pragma unroll
        for (int mi = 0; mi < 2; mi++)
#pragma unroll
            for (int nf = 0; nf < 8; nf++) {
                int col = c0 + nf * 8;
                float b0 = bias[col], b1 = bias[col + 1];
#pragma unroll
                for (int hh = 0; hh < 2; hh++) {
                    int r = r0 + mi * 16 + hh * 8;
                    float2 v;
                    v.x = acc[mi][nf][hh * 2 + 0] + b0;
                    v.y = acc[mi][nf][hh * 2 + 1] + b1;
                    *(float2*)(op + (size_t)r * DSZ + dbase + col) = v;
                }
            }
    }
}

// ---------------- GEMM 2: omg = 1 - sigmoid(g1 @ Wg2 + bg2) --------------------
__global__ __launch_bounds__(256) void gemm2_k(const float* __restrict__ bg2)
{
    extern __shared__ char sm[];
    uint32_t s0 = smem_u32(sm);

    const int mbase = blockIdx.x * 128;
    const int s = blockIdx.y >> 1;
    const int dbase = (blockIdx.y & 1) * 128;

    const __half* gA = g1f16_g + ((size_t)s * MTOT + mbase) * DSZ;
    const __half* gB = w2f16_g + ((size_t)s * DSZ + dbase) * DSZ;

    float acc[2][8][4];
    gemm_pipeline<DSZ / KCH>(gA, gB, DSZ, s0, acc);

    const int lane = threadIdx.x & 31, warp = threadIdx.x >> 5;
    const int wm = warp & 3, wn = warp >> 2;
    const int r0 = mbase + wm * 32 + (lane >> 2);
    const int c0 = wn * 64 + (lane & 3) * 2;
    const float* bias = bg2 + s * DSZ + dbase;
    float* op = omg_g + (size_t)s * MTOT * DSZ;

#pragma unroll
    for (int mi = 0; mi < 2; mi++)
#pragma unroll
        for (int nf = 0; nf < 8; nf++) {
            int col = c0 + nf * 8;
            float b0 = bias[col], b1 = bias[col + 1];
#pragma unroll
            for (int hh = 0; hh < 2; hh++) {
                int r = r0 + mi * 16 + hh * 8;
                float2 v;
                v.x = 1.0f / (1.0f + expf(acc[mi][nf][hh * 2 + 0] + b0));
                v.y = 1.0f / (1.0f + expf(acc[mi][nf][hh * 2 + 1] + b1));
                *(float2*)(op + (size_t)r * DSZ + dbase + col) = v;
            }
        }
}

// ---------------- conversion kernels -------------------------------------------
__global__ __launch_bounds__(256) void conv_x_k(const float* __restrict__ x) {
    size_t i = ((size_t)blockIdx.x * 256 + threadIdx.x) * 4;
    float4 v = *(const float4*)(x + i);
    union { __half h[4]; uint2 u; } p;
    p.h[0] = __float2half_rn(v.x);
    p.h[1] = __float2half_rn(v.y);
    p.h[2] = __float2half_rn(v.z);
    p.h[3] = __float2half_rn(v.w);
    *(uint2*)(xh_g + i) = p.u;
}

__global__ void conv_w1_k(const float* __restrict__ src, int zbase, int kdim) {
    __shared__ float t[32][33];
    int z = blockIdx.z;
    const float* sp = src + (size_t)z * kdim * DSZ;
    int tx = threadIdx.x, ty = threadIdx.y;
    int k0 = blockIdx.x * 32, d0 = blockIdx.y * 32;
#pragma unroll
    for (int i = 0; i < 4; i++)
        t[ty + i * 8][tx] = sp[(size_t)(k0 + ty + i * 8) * DSZ + d0 + tx];
    __syncthreads();
    __half* oh = (kdim == DIN ? w1f16_g + (size_t)(zbase + z) * DSZ * DIN
                              : w2f16_g + (size_t)z * DSZ * DSZ);
#pragma unroll
    for (int i = 0; i < 4; i++) {
        int n = d0 + ty + i * 8, k = k0 + tx;
        oh[(size_t)n * kdim + k] = __float2half_rn(t[tx][ty + i * 8]);
    }
}

// ---------------- segmented scan (3 phases) ------------------------------------
struct ScanConsts { float abr[4], abi[4], bsc[4]; };

__global__ __launch_bounds__(256) void scan_p1(ScanConsts c) {
    const int idx = blockIdx.x;                 // b*64 + s*16 + seg
    const int seg = idx & 15, s = (idx >> 4) & 3, b = idx >> 6;
    const int d = threadIdx.x;
    const float abr = c.abr[s], abi = c.abi[s], bs = c.bsc[s];
    const size_t base = ((size_t)s * MTOT + (size_t)b * 4096 + seg * 256) * DSZ + d;
    float Ar = 1.f, Ai = 0.f, Hr = 0.f, Hi = 0.f;
#pragma unroll 4
    for (int t = 0; t < 256; t++) {
        size_t off = base + (size_t)t * DSZ;
        float w  = omg_g[off];
        float xr = dre_g[off];
        float xi = dim_g[off];
        float ar = w * abr, ai = w * abi, wb = w * bs;
        float br = wb * xr, bi = wb * xi;
        float nHr = fmaf(ar, Hr, fmaf(-ai, Hi, br));
        float nHi = fmaf(ar, Hi, fmaf( ai, Hr, bi));
        float nAr = fmaf(ar, Ar, -ai * Ai);
        float nAi = fmaf(ar, Ai,  ai * Ar);
        Hr = nHr; Hi = nHi; Ar = nAr; Ai = nAi;
    }
    Aseg_g[idx * 256 + d] = make_float2(Ar, Ai);
    Hseg_g[idx * 256 + d] = make_float2(Hr, Hi);
}

__global__ __launch_bounds__(256) void scan_p2() {
    const int bs_ = blockIdx.x;                 // b*4 + s
    const int d = threadIdx.x;
    float cr = 0.f, ci = 0.f;
#pragma unroll
    for (int g = 0; g < 16; g++) {
        int idx = (bs_ * 16 + g) * 256 + d;
        Ini_g[idx] = make_float2(cr, ci);
        float2 A = Aseg_g[idx];
        float2 H = Hseg_g[idx];
        float ncr = fmaf(A.x, cr, fmaf(-A.y, ci, H.x));
        float nci = fmaf(A.x, ci, fmaf( A.y, cr, H.y));
        cr = ncr; ci = nci;
    }
}

__global__ __launch_bounds__(256) void scan_p3(float* __restrict__ out, ScanConsts c) {
    const int idx = blockIdx.x;
    const int seg = idx & 15, s = (idx >> 4) & 3, b = idx >> 6;
    const int d = threadIdx.x;
    const float abr = c.abr[s], abi = c.abi[s], bs = c.bsc[s];
    const size_t base = ((size_t)s * MTOT + (size_t)b * 4096 + seg * 256) * DSZ + d;
    float2 h0 = Ini_g[idx * 256 + d];
    float hr = h0.x, hi = h0.y;
    float* op = out + ((size_t)b * 4096 + seg * 256) * 2048 + (size_t)s * 512 + d;
#pragma unroll 4
    for (int t = 0; t < 256; t++) {
        size_t off = base + (size_t)t * DSZ;
        float w  = omg_g[off];
        float xr = dre_g[off];
        float xi = dim_g[off];
        float ar = w * abr, ai = w * abi, wb = w * bs;
        float br = wb * xr, bi = wb * xi;
        float nhr = fmaf(ar, hr, fmaf(-ai, hi, br));
        float nhi = fmaf(ar, hi, fmaf( ai, hr, bi));
        hr = nhr; hi = nhi;
        op[(size_t)t * 2048]       = hr;
        op[(size_t)t * 2048 + 256] = hi;
    }
}

// ---------------- host ----------------------------------------------------------
extern "C" void kernel_launch(void* const* d_in, const int* in_sizes, int n_in,
                              void* d_out, int out_size)
{
    const float* x   = (const float*)d_in[0];
    const float* Wg1 = (const float*)d_in[1];
    const float* bg1 = (const float*)d_in[2];
    const float* Wg2 = (const float*)d_in[3];
    const float* bg2 = (const float*)d_in[4];
    const float* Wdr = (const float*)d_in[5];
    const float* bdr = (const float*)d_in[6];
    const float* Wdi = (const float*)d_in[7];
    const float* bdi = (const float*)d_in[8];
    float* out = (float*)d_out;

    cudaFuncSetAttribute(gemm1_k, cudaFuncAttributeMaxDynamicSharedMemorySize, SMEM_SZ);
    cudaFuncSetAttribute(gemm2_k, cudaFuncAttributeMaxDynamicSharedMemorySize, SMEM_SZ);

    conv_x_k<<<(int)(((size_t)MTOT * DIN) / 1024), 256>>>(x);
    dim3 tb(32, 8);
    conv_w1_k<<<dim3(32, 8, 4), tb>>>(Wg1, 0, DIN);
    conv_w1_k<<<dim3(32, 8, 4), tb>>>(Wdr, 4, DIN);
    conv_w1_k<<<dim3(32, 8, 4), tb>>>(Wdi, 8, DIN);
    conv_w1_k<<<dim3(8, 8, 4), tb>>>(Wg2, 0, DSZ);

    gemm1_k<<<dim3(MTOT / 128, 24), 256, SMEM_SZ>>>(bg1, bdr, bdi);
    gemm2_k<<<dim3(MTOT / 128, 8), 256, SMEM_SZ>>>(bg2);

    ScanConsts c;
    const double r [4] = {1.0, 0.999, 0.9495, 0.9};
    const double th[4] = {0.0, 0.01,  0.505,  1.0};
    for (int s = 0; s < 4; s++) {
        c.abr[s] = (float)(r[s] * cos(th[s]));
        c.abi[s] = (float)(r[s] * sin(th[s]));
        c.bsc[s] = (float)((r[s] >= 1.0) ? (1.0 / 16.0) : (1.0 - r[s]));
    }
    scan_p1<<<256, 256>>>(c);
    scan_p2<<<16, 256>>>();
    scan_p3<<<256, 256>>>(out, c);
}